// round 5
// baseline (speedup 1.0000x reference)
#include <cuda_runtime.h>
#include <cstdint>

// Problem constants
#define KS    5
#define NTAP  25
#define OH    508
#define OW    508
#define IH    512
#define IW    512
#define CI    3
#define BATCH 8

#define PLANE  (OH * OW)        // 258064 floats, %4 == 0
#define PLANE4 (PLANE / 4)
#define WTOT   6193536          // 8*3*508*508

// Tile config
#define TW4   32                // float4 columns per tile (x)
#define TWPX  (TW4 * 4)         // 128 pixels wide
#define TH    8                 // rows per tile
#define SW    (TWPX + 4)        // 132 floats per smem row
#define SROWS (TH + 4)          // 12 rows
#define NTHR  (TW4 * TH)        // 256

#define RING  4                 // tap-row ring depth (rows in flight = 3)

// Dynamic SMEM layout: tensor tile | RING-deep tap-row ring
#define ST_BYTES   (CI * SROWS * SW * 4)        // 19008
#define SK_OFF     ST_BYTES                     // 16B aligned
#define ROW_SLOTS  (KS * NTHR)                  // 1280 float4 per row buffer
#define SK_BYTES   (RING * ROW_SLOTS * 16)      // 81920
#define SMEM_BYTES (SK_OFF + SK_BYTES)          // 100928

__device__ __forceinline__ void cp16(uint32_t dst_smem, const void* src) {
    asm volatile("cp.async.cg.shared.global [%0], [%1], 16;\n"
                 :: "r"(dst_smem), "l"(src));
}
__device__ __forceinline__ void cp_commit() {
    asm volatile("cp.async.commit_group;\n" ::: "memory");
}
template <int N>
__device__ __forceinline__ void cp_wait() {
    asm volatile("cp.async.wait_group %0;\n" :: "n"(N) : "memory");
}
__device__ __forceinline__ void stcs4(float* p, float4 v) {
    asm volatile("st.global.cs.v4.f32 [%0], {%1,%2,%3,%4};\n"
                 :: "l"(p), "f"(v.x), "f"(v.y), "f"(v.z), "f"(v.w));
}

__global__ __launch_bounds__(NTHR, 2)
void apply_kernels_k(const float* __restrict__ kern,   // [8][25][508][508]
                     const float* __restrict__ tens,   // [8][3][512][512]
                     float* __restrict__ out)          // weighted ++ kernel_sum
{
    extern __shared__ char smem_raw[];
    float  (*s_t)[SROWS][SW] = reinterpret_cast<float(*)[SROWS][SW]>(smem_raw);
    float4* s_k              = reinterpret_cast<float4*>(smem_raw + SK_OFF);

    const int b  = blockIdx.z;
    const int i0 = blockIdx.y * TH;
    const int j0 = blockIdx.x * TWPX;

    const int tx  = threadIdx.x;
    const int ty  = threadIdx.y;
    const int tid = ty * TW4 + tx;
    // clamp instead of early-return: out-of-range threads duplicate valid work
    const int i  = min(i0 + ty, OH - 1);
    const int j  = min(j0 + tx * 4, OW - 4);

    const float4* kp = reinterpret_cast<const float4*>(
        kern + ((size_t)b * NTAP) * PLANE + (size_t)i * OW + j);

    const uint32_t skbase = (uint32_t)__cvta_generic_to_shared(s_k);

    // ---- prestage tap rows 0..3 (4 groups, 20 LDGSTS, zero registers) ----
    #pragma unroll
    for (int r = 0; r < RING; ++r) {
        #pragma unroll
        for (int t = 0; t < KS; ++t)
            cp16(skbase + (uint32_t)((r % RING) * ROW_SLOTS + t * NTHR + tid) * 16u,
                 kp + (r * KS + t) * PLANE4);
        cp_commit();
    }

    // ---- cooperative tensor tile load (3 ch, 12 rows, 132 cols) ----
    {
        const int NV4 = CI * SROWS * (SW / 4);   // 1188 float4 slots
        #pragma unroll 1
        for (int idx = tid; idx < NV4; idx += NTHR) {
            const int c    = idx / (SROWS * (SW / 4));
            const int rem  = idx % (SROWS * (SW / 4));
            const int r    = rem / (SW / 4);
            const int q4   = rem % (SW / 4);
            const int grow = i0 + r;
            const int gcol = j0 + q4 * 4;
            float4 v = make_float4(0.f, 0.f, 0.f, 0.f);
            if (grow < IH && gcol < IW) {
                v = *reinterpret_cast<const float4*>(
                        &tens[(((size_t)b * CI + c) * IH + grow) * IW + gcol]);
            }
            *reinterpret_cast<float4*>(&s_t[c][r][q4 * 4]) = v;
        }
    }
    __syncthreads();

    const int li = i - i0;
    const int lj = j - j0;

    float acc0[4] = {0.f, 0.f, 0.f, 0.f};
    float acc1[4] = {0.f, 0.f, 0.f, 0.f};
    float acc2[4] = {0.f, 0.f, 0.f, 0.f};
    float ssum[4] = {0.f, 0.f, 0.f, 0.f};

    #pragma unroll
    for (int di = 0; di < KS; ++di) {
        // ---- wait until row di has landed (keep up to 3 rows in flight) ----
        if (di == 0)      cp_wait<3>();
        else if (di == 1) cp_wait<3>();
        else if (di == 2) cp_wait<2>();
        else if (di == 3) cp_wait<1>();
        else              cp_wait<0>();

        // ---- register-cache the 8 tensor floats per channel for this row ----
        float r0[8], r1[8], r2[8];
        {
            float4 a, bb;
            a  = *reinterpret_cast<const float4*>(&s_t[0][li + di][lj]);
            bb = *reinterpret_cast<const float4*>(&s_t[0][li + di][lj + 4]);
            r0[0]=a.x; r0[1]=a.y; r0[2]=a.z; r0[3]=a.w;
            r0[4]=bb.x; r0[5]=bb.y; r0[6]=bb.z; r0[7]=bb.w;
            a  = *reinterpret_cast<const float4*>(&s_t[1][li + di][lj]);
            bb = *reinterpret_cast<const float4*>(&s_t[1][li + di][lj + 4]);
            r1[0]=a.x; r1[1]=a.y; r1[2]=a.z; r1[3]=a.w;
            r1[4]=bb.x; r1[5]=bb.y; r1[6]=bb.z; r1[7]=bb.w;
            a  = *reinterpret_cast<const float4*>(&s_t[2][li + di][lj]);
            bb = *reinterpret_cast<const float4*>(&s_t[2][li + di][lj + 4]);
            r2[0]=a.x; r2[1]=a.y; r2[2]=a.z; r2[3]=a.w;
            r2[4]=bb.x; r2[5]=bb.y; r2[6]=bb.z; r2[7]=bb.w;
        }

        // ---- consume row di from its ring slot (own slots, conflict-free) ----
        const int slot = (di % RING) * ROW_SLOTS;
        #pragma unroll
        for (int dj = 0; dj < KS; ++dj) {
            const float4 k4 = s_k[slot + dj * NTHR + tid];
            const float kv[4] = {k4.x, k4.y, k4.z, k4.w};
            #pragma unroll
            for (int l = 0; l < 4; ++l) {
                const float s = kv[l];
                ssum[l] += s;
                acc0[l] = fmaf(s, r0[l + dj], acc0[l]);
                acc1[l] = fmaf(s, r1[l + dj], acc1[l]);
                acc2[l] = fmaf(s, r2[l + dj], acc2[l]);
            }
        }

        // ---- stage row di+4 into the slot just freed ----
        if (di + RING < KS) {   // only di==0 stages row 4
            #pragma unroll
            for (int t = 0; t < KS; ++t)
                cp16(skbase + (uint32_t)(((di + RING) % RING) * ROW_SLOTS + t * NTHR + tid) * 16u,
                     kp + ((di + RING) * KS + t) * PLANE4);
            cp_commit();
        }
    }

    // ---- stores: weighted (3 channels) then kernel_sum (streaming hint) ----
    const size_t pix = (size_t)i * OW + j;
    stcs4(&out[(((size_t)b * CI + 0) * (size_t)PLANE) + pix],
          make_float4(acc0[0], acc0[1], acc0[2], acc0[3]));
    stcs4(&out[(((size_t)b * CI + 1) * (size_t)PLANE) + pix],
          make_float4(acc1[0], acc1[1], acc1[2], acc1[3]));
    stcs4(&out[(((size_t)b * CI + 2) * (size_t)PLANE) + pix],
          make_float4(acc2[0], acc2[1], acc2[2], acc2[3]));
    stcs4(&out[WTOT + (size_t)b * (size_t)PLANE + pix],
          make_float4(ssum[0], ssum[1], ssum[2], ssum[3]));
}

extern "C" void kernel_launch(void* const* d_in, const int* in_sizes, int n_in,
                              void* d_out, int out_size)
{
    const float* kern = (const float*)d_in[0];   // (8, 25, 508, 508)
    const float* tens = (const float*)d_in[1];   // (8, 3, 512, 512)
    float* out = (float*)d_out;

    cudaFuncSetAttribute(apply_kernels_k,
                         cudaFuncAttributeMaxDynamicSharedMemorySize, SMEM_BYTES);

    dim3 block(TW4, TH, 1);                       // 256 threads
    dim3 grid((OW / 4 + TW4 - 1) / TW4,           // 4
              (OH + TH - 1) / TH,                 // 64
              BATCH);                             // 8
    apply_kernels_k<<<grid, block, SMEM_BYTES>>>(kern, tens, out);
}

// round 6
// speedup vs baseline: 1.2507x; 1.2507x over previous
#include <cuda_runtime.h>
#include <cstdint>

// Problem constants
#define KS    5
#define NTAP  25
#define OH    508
#define OW    508
#define IH    512
#define IW    512
#define CI    3
#define BATCH 8
#define PLANE (OH * OW)              // 258064
#define WTOT  (BATCH * CI * PLANE)   // 6193536

// Band decomposition: each CTA = TH full-width output rows of one batch
#define TH     2
#define NBAND  (OH / TH)             // 254
#define NTHR   128
#define NF4    (TH * (OW / 4))       // 254 float4 outputs per CTA

// SMEM layout (dynamic)
#define TROWS       (TH + 4)                      // 6 tensor rows
#define TILE_BYTES  (CI * TROWS * IW * 4)         // 36864
#define TAPB        (TH * OW * 4)                 // 4064 B contiguous per tap
#define STAGE_BYTES (KS * TAPB)                   // 20320
#define RING        3
#define RING_OFF    TILE_BYTES                    // 36864 (16B aligned)
#define MBAR_OFF    (RING_OFF + RING * STAGE_BYTES)  // 97824
#define SMEM_BYTES  (MBAR_OFF + 64)               // 97888

// ---- PTX helpers ----
__device__ __forceinline__ void mbar_init(uint32_t a, uint32_t cnt) {
    asm volatile("mbarrier.init.shared.b64 [%0], %1;" :: "r"(a), "r"(cnt) : "memory");
}
__device__ __forceinline__ void mbar_expect_tx(uint32_t a, uint32_t bytes) {
    asm volatile("mbarrier.arrive.expect_tx.shared.b64 _, [%0], %1;"
                 :: "r"(a), "r"(bytes) : "memory");
}
__device__ __forceinline__ void mbar_arrive(uint32_t a) {
    asm volatile("mbarrier.arrive.shared.b64 _, [%0];" :: "r"(a) : "memory");
}
__device__ __forceinline__ void mbar_wait(uint32_t a, uint32_t parity) {
    asm volatile(
        "{\n\t.reg .pred P1;\n\t"
        "WAIT_%=:\n\t"
        "mbarrier.try_wait.parity.acquire.cta.shared::cta.b64 P1, [%0], %1, 0x989680;\n\t"
        "@P1 bra.uni DONE_%=;\n\t"
        "bra.uni WAIT_%=;\n\t"
        "DONE_%=:\n\t}"
        :: "r"(a), "r"(parity) : "memory");
}
__device__ __forceinline__ void bulk_g2s(uint32_t dst, const void* src,
                                         uint32_t bytes, uint32_t mbar) {
    asm volatile(
        "cp.async.bulk.shared::cluster.global.mbarrier::complete_tx::bytes "
        "[%0], [%1], %2, [%3];"
        :: "r"(dst), "l"(src), "r"(bytes), "r"(mbar) : "memory");
}

__global__ __launch_bounds__(NTHR, 2)
void apply_kernels_k(const float* __restrict__ kern,   // [8][25][508][508]
                     const float* __restrict__ tens,   // [8][3][512][512]
                     float* __restrict__ out)          // weighted ++ kernel_sum
{
    extern __shared__ char smem[];
    float* smem_f = reinterpret_cast<float*>(smem);
    const uint32_t sbase = (uint32_t)__cvta_generic_to_shared(smem);

    const int band = blockIdx.x;          // 0..253
    const int b    = blockIdx.y;          // 0..7
    const int i0   = band * TH;
    const int tid  = threadIdx.x;

    // mbarrier addresses
    const uint32_t mb_tile  = sbase + MBAR_OFF;
    const uint32_t mb_full0 = sbase + MBAR_OFF + 8;    // +8*s for slot s
    const uint32_t mb_emp0  = sbase + MBAR_OFF + 32;   // +8*s for slot s

    if (tid == 0) {
        mbar_init(mb_tile, 1);
        #pragma unroll
        for (int s = 0; s < RING; ++s) {
            mbar_init(mb_full0 + 8u * s, 1);
            mbar_init(mb_emp0  + 8u * s, NTHR);
        }
    }
    __syncthreads();

    // ---- producer prologue: tile + first 3 tap rows, all bulk-async ----
    if (tid == 0) {
        mbar_expect_tx(mb_tile, TILE_BYTES);
        #pragma unroll
        for (int c = 0; c < CI; ++c)
            #pragma unroll
            for (int r = 0; r < TROWS; ++r)
                bulk_g2s(sbase + (uint32_t)((c * TROWS + r) * IW * 4),
                         tens + (((size_t)b * CI + c) * IH + (i0 + r)) * IW,
                         IW * 4, mb_tile);
        #pragma unroll
        for (int s = 0; s < RING; ++s) {
            mbar_expect_tx(mb_full0 + 8u * s, STAGE_BYTES);
            #pragma unroll
            for (int t = 0; t < KS; ++t)
                bulk_g2s(sbase + (uint32_t)(RING_OFF + s * STAGE_BYTES + t * TAPB),
                         kern + ((size_t)b * NTAP + (s * KS + t)) * PLANE + (size_t)i0 * OW,
                         TAPB, mb_full0 + 8u * s);
        }
    }

    // ---- per-thread output assignment: f and f+128 (clamped dup for 126/127)
    const int f0  = tid;                    // 0..127  (<254)
    const int f1  = min(tid + NTHR, NF4 - 1);
    const int ro0 = f0 / (OW / 4), c40 = f0 % (OW / 4);
    const int ro1 = f1 / (OW / 4), c41 = f1 % (OW / 4);

    float a0[CI][4], a1[CI][4], ss0[4], ss1[4];
    #pragma unroll
    for (int c = 0; c < CI; ++c)
        #pragma unroll
        for (int l = 0; l < 4; ++l) { a0[c][l] = 0.f; a1[c][l] = 0.f; }
    #pragma unroll
    for (int l = 0; l < 4; ++l) { ss0[l] = 0.f; ss1[l] = 0.f; }

    mbar_wait(mb_tile, 0);                  // tensor tile ready

    #pragma unroll
    for (int di = 0; di < KS; ++di) {
        const int slot = di % RING;
        mbar_wait(mb_full0 + 8u * slot, (di < RING) ? 0u : 1u);

        const char* ringp = smem + RING_OFF + slot * STAGE_BYTES;

        // output 0
        {
            float r[CI][8];
            #pragma unroll
            for (int c = 0; c < CI; ++c) {
                const float4 ta = *reinterpret_cast<const float4*>(
                    &smem_f[(c * TROWS + ro0 + di) * IW + c40 * 4]);
                const float4 tb = *reinterpret_cast<const float4*>(
                    &smem_f[(c * TROWS + ro0 + di) * IW + c40 * 4 + 4]);
                r[c][0]=ta.x; r[c][1]=ta.y; r[c][2]=ta.z; r[c][3]=ta.w;
                r[c][4]=tb.x; r[c][5]=tb.y; r[c][6]=tb.z; r[c][7]=tb.w;
            }
            #pragma unroll
            for (int dj = 0; dj < KS; ++dj) {
                const float4 k4 = *reinterpret_cast<const float4*>(
                    ringp + dj * TAPB + ro0 * (OW * 4) + c40 * 16);
                const float kv[4] = {k4.x, k4.y, k4.z, k4.w};
                #pragma unroll
                for (int l = 0; l < 4; ++l) {
                    ss0[l] += kv[l];
                    #pragma unroll
                    for (int c = 0; c < CI; ++c)
                        a0[c][l] = fmaf(kv[l], r[c][l + dj], a0[c][l]);
                }
            }
        }
        // output 1
        {
            float r[CI][8];
            #pragma unroll
            for (int c = 0; c < CI; ++c) {
                const float4 ta = *reinterpret_cast<const float4*>(
                    &smem_f[(c * TROWS + ro1 + di) * IW + c41 * 4]);
                const float4 tb = *reinterpret_cast<const float4*>(
                    &smem_f[(c * TROWS + ro1 + di) * IW + c41 * 4 + 4]);
                r[c][0]=ta.x; r[c][1]=ta.y; r[c][2]=ta.z; r[c][3]=ta.w;
                r[c][4]=tb.x; r[c][5]=tb.y; r[c][6]=tb.z; r[c][7]=tb.w;
            }
            #pragma unroll
            for (int dj = 0; dj < KS; ++dj) {
                const float4 k4 = *reinterpret_cast<const float4*>(
                    ringp + dj * TAPB + ro1 * (OW * 4) + c41 * 16);
                const float kv[4] = {k4.x, k4.y, k4.z, k4.w};
                #pragma unroll
                for (int l = 0; l < 4; ++l) {
                    ss1[l] += kv[l];
                    #pragma unroll
                    for (int c = 0; c < CI; ++c)
                        a1[c][l] = fmaf(kv[l], r[c][l + dj], a1[c][l]);
                }
            }
        }

        mbar_arrive(mb_emp0 + 8u * slot);

        // stage row di+RING into the slot just emptied
        if (di < KS - RING) {               // di == 0, 1
            if (tid == 0) {
                mbar_wait(mb_emp0 + 8u * slot, 0);
                mbar_expect_tx(mb_full0 + 8u * slot, STAGE_BYTES);
                #pragma unroll
                for (int t = 0; t < KS; ++t)
                    bulk_g2s(sbase + (uint32_t)(RING_OFF + slot * STAGE_BYTES + t * TAPB),
                             kern + ((size_t)b * NTAP + ((di + RING) * KS + t)) * PLANE
                                  + (size_t)i0 * OW,
                             TAPB, mb_full0 + 8u * slot);
            }
        }
    }

    // ---- stores ----
    {
        const int i = i0 + ro0, j = c40 * 4;
        const size_t pix = (size_t)i * OW + j;
        #pragma unroll
        for (int c = 0; c < CI; ++c)
            *reinterpret_cast<float4*>(&out[((size_t)b * CI + c) * PLANE + pix]) =
                make_float4(a0[c][0], a0[c][1], a0[c][2], a0[c][3]);
        *reinterpret_cast<float4*>(&out[WTOT + (size_t)b * PLANE + pix]) =
            make_float4(ss0[0], ss0[1], ss0[2], ss0[3]);
    }
    {
        const int i = i0 + ro1, j = c41 * 4;
        const size_t pix = (size_t)i * OW + j;
        #pragma unroll
        for (int c = 0; c < CI; ++c)
            *reinterpret_cast<float4*>(&out[((size_t)b * CI + c) * PLANE + pix]) =
                make_float4(a1[c][0], a1[c][1], a1[c][2], a1[c][3]);
        *reinterpret_cast<float4*>(&out[WTOT + (size_t)b * PLANE + pix]) =
            make_float4(ss1[0], ss1[1], ss1[2], ss1[3]);
    }
}

extern "C" void kernel_launch(void* const* d_in, const int* in_sizes, int n_in,
                              void* d_out, int out_size)
{
    const float* kern = (const float*)d_in[0];   // (8, 25, 508, 508)
    const float* tens = (const float*)d_in[1];   // (8, 3, 512, 512)
    float* out = (float*)d_out;

    cudaFuncSetAttribute(apply_kernels_k,
                         cudaFuncAttributeMaxDynamicSharedMemorySize, SMEM_BYTES);

    dim3 block(NTHR, 1, 1);                  // 128 threads
    dim3 grid(NBAND, BATCH, 1);              // 254 x 8 = 2032 CTAs
    apply_kernels_k<<<grid, block, SMEM_BYTES>>>(kern, tens, out);
}

// round 7
// speedup vs baseline: 1.2676x; 1.0136x over previous
#include <cuda_runtime.h>
#include <cstdint>

// Problem constants
#define KS    5
#define NTAP  25
#define OH    508
#define OW    508
#define IH    512
#define IW    512
#define CI    3
#define BATCH 8
#define PLANE (OH * OW)              // 258064
#define WTOT  (BATCH * CI * PLANE)   // 6193536

// Band decomposition: each CTA = TH full-width output rows of one batch
#define TH     2
#define NBAND  (OH / TH)             // 254
#define NTHR   256
#define NF4    (TH * (OW / 4))       // 254 float4 outputs per CTA

// SMEM layout (dynamic)
#define TROWS       (TH + 4)                      // 6 tensor rows
#define TILE_BYTES  (CI * TROWS * IW * 4)         // 36864
#define TAPB        (TH * OW * 4)                 // 4064 B contiguous per tap
#define NSLOT       8                             // tap-granular ring
#define RING_OFF    TILE_BYTES                    // 36864 (16B aligned)
#define MBAR_OFF    (RING_OFF + NSLOT * TAPB)     // 69376
#define SMEM_BYTES  (MBAR_OFF + 160)              // 69536

// ---- PTX helpers ----
__device__ __forceinline__ void mbar_init(uint32_t a, uint32_t cnt) {
    asm volatile("mbarrier.init.shared.b64 [%0], %1;" :: "r"(a), "r"(cnt) : "memory");
}
__device__ __forceinline__ void mbar_expect_tx(uint32_t a, uint32_t bytes) {
    asm volatile("mbarrier.arrive.expect_tx.shared.b64 _, [%0], %1;"
                 :: "r"(a), "r"(bytes) : "memory");
}
__device__ __forceinline__ void mbar_arrive(uint32_t a) {
    asm volatile("mbarrier.arrive.shared.b64 _, [%0];" :: "r"(a) : "memory");
}
__device__ __forceinline__ void mbar_wait(uint32_t a, uint32_t parity) {
    asm volatile(
        "{\n\t.reg .pred P1;\n\t"
        "WAIT_%=:\n\t"
        "mbarrier.try_wait.parity.acquire.cta.shared::cta.b64 P1, [%0], %1, 0x989680;\n\t"
        "@P1 bra.uni DONE_%=;\n\t"
        "bra.uni WAIT_%=;\n\t"
        "DONE_%=:\n\t}"
        :: "r"(a), "r"(parity) : "memory");
}
__device__ __forceinline__ void bulk_g2s(uint32_t dst, const void* src,
                                         uint32_t bytes, uint32_t mbar) {
    asm volatile(
        "cp.async.bulk.shared::cluster.global.mbarrier::complete_tx::bytes "
        "[%0], [%1], %2, [%3];"
        :: "r"(dst), "l"(src), "r"(bytes), "r"(mbar) : "memory");
}

__global__ __launch_bounds__(NTHR, 3)
void apply_kernels_k(const float* __restrict__ kern,   // [8][25][508][508]
                     const float* __restrict__ tens,   // [8][3][512][512]
                     float* __restrict__ out)          // weighted ++ kernel_sum
{
    extern __shared__ char smem[];
    float* smem_f = reinterpret_cast<float*>(smem);
    const uint32_t sbase = (uint32_t)__cvta_generic_to_shared(smem);

    const int band = blockIdx.x;          // 0..253
    const int b    = blockIdx.y;          // 0..7
    const int i0   = band * TH;
    const int tid  = threadIdx.x;

    // mbarrier addresses: tile | full[8] | empty[8]
    const uint32_t mb_tile  = sbase + MBAR_OFF;
    const uint32_t mb_full0 = sbase + MBAR_OFF + 8;
    const uint32_t mb_emp0  = sbase + MBAR_OFF + 8 + 8 * NSLOT;

    if (tid == 0) {
        mbar_init(mb_tile, 1);
        #pragma unroll
        for (int s = 0; s < NSLOT; ++s) {
            mbar_init(mb_full0 + 8u * s, 1);
            mbar_init(mb_emp0  + 8u * s, NTHR);
        }
    }
    __syncthreads();

    const float* kband = kern + (size_t)b * NTAP * PLANE + (size_t)i0 * OW;

    // ---- producer prologue: tensor tile + first 8 taps, all bulk-async ----
    if (tid == 0) {
        mbar_expect_tx(mb_tile, TILE_BYTES);
        #pragma unroll
        for (int c = 0; c < CI; ++c)
            #pragma unroll
            for (int r = 0; r < TROWS; ++r)
                bulk_g2s(sbase + (uint32_t)((c * TROWS + r) * IW * 4),
                         tens + (((size_t)b * CI + c) * IH + (i0 + r)) * IW,
                         IW * 4, mb_tile);
        #pragma unroll
        for (int t = 0; t < NSLOT; ++t) {
            mbar_expect_tx(mb_full0 + 8u * t, TAPB);
            bulk_g2s(sbase + (uint32_t)(RING_OFF + t * TAPB),
                     kband + (size_t)t * PLANE, TAPB, mb_full0 + 8u * t);
        }
    }

    // ---- one float4 output per thread (threads 254/255 duplicate 253) ----
    const int f  = min(tid, NF4 - 1);
    const int ro = f / (OW / 4);
    const int c4 = f % (OW / 4);

    float acc[CI][4], ss[4];
    #pragma unroll
    for (int c = 0; c < CI; ++c)
        #pragma unroll
        for (int l = 0; l < 4; ++l) acc[c][l] = 0.f;
    #pragma unroll
    for (int l = 0; l < 4; ++l) ss[l] = 0.f;

    float rT[CI][8];

    mbar_wait(mb_tile, 0);                  // tensor tile ready

    #pragma unroll
    for (int tap = 0; tap < NTAP; ++tap) {
        const int di   = tap / KS;
        const int dj   = tap % KS;
        const int slot = tap % NSLOT;
        const uint32_t par = (uint32_t)((tap / NSLOT) & 1);

        mbar_wait(mb_full0 + 8u * slot, par);

        // refresh tensor register cache at each new kernel row
        if (dj == 0) {
            #pragma unroll
            for (int c = 0; c < CI; ++c) {
                const float4 ta = *reinterpret_cast<const float4*>(
                    &smem_f[(c * TROWS + ro + di) * IW + c4 * 4]);
                const float4 tb = *reinterpret_cast<const float4*>(
                    &smem_f[(c * TROWS + ro + di) * IW + c4 * 4 + 4]);
                rT[c][0]=ta.x; rT[c][1]=ta.y; rT[c][2]=ta.z; rT[c][3]=ta.w;
                rT[c][4]=tb.x; rT[c][5]=tb.y; rT[c][6]=tb.z; rT[c][7]=tb.w;
            }
        }

        const float4 k4 = *reinterpret_cast<const float4*>(
            smem + RING_OFF + slot * TAPB + ro * (OW * 4) + c4 * 16);
        const float kv[4] = {k4.x, k4.y, k4.z, k4.w};
        #pragma unroll
        for (int l = 0; l < 4; ++l) {
            ss[l] += kv[l];
            #pragma unroll
            for (int c = 0; c < CI; ++c)
                acc[c][l] = fmaf(kv[l], rT[c][l + dj], acc[c][l]);
        }

        mbar_arrive(mb_emp0 + 8u * slot);

        // refill this slot with tap+8 once all 256 threads consumed it
        if (tap + NSLOT < NTAP) {
            if (tid == 0) {
                mbar_wait(mb_emp0 + 8u * slot, par);
                mbar_expect_tx(mb_full0 + 8u * slot, TAPB);
                bulk_g2s(sbase + (uint32_t)(RING_OFF + slot * TAPB),
                         kband + (size_t)(tap + NSLOT) * PLANE,
                         TAPB, mb_full0 + 8u * slot);
            }
        }
    }

    // ---- stores ----
    const int i = i0 + ro, j = c4 * 4;
    const size_t pix = (size_t)i * OW + j;
    #pragma unroll
    for (int c = 0; c < CI; ++c)
        *reinterpret_cast<float4*>(&out[((size_t)b * CI + c) * PLANE + pix]) =
            make_float4(acc[c][0], acc[c][1], acc[c][2], acc[c][3]);
    *reinterpret_cast<float4*>(&out[WTOT + (size_t)b * PLANE + pix]) =
        make_float4(ss[0], ss[1], ss[2], ss[3]);
}

extern "C" void kernel_launch(void* const* d_in, const int* in_sizes, int n_in,
                              void* d_out, int out_size)
{
    const float* kern = (const float*)d_in[0];   // (8, 25, 508, 508)
    const float* tens = (const float*)d_in[1];   // (8, 3, 512, 512)
    float* out = (float*)d_out;

    cudaFuncSetAttribute(apply_kernels_k,
                         cudaFuncAttributeMaxDynamicSharedMemorySize, SMEM_BYTES);

    dim3 block(NTHR, 1, 1);                  // 256 threads
    dim3 grid(NBAND, BATCH, 1);              // 254 x 8 = 2032 CTAs
    apply_kernels_k<<<grid, block, SMEM_BYTES>>>(kern, tens, out);
}

// round 8
// speedup vs baseline: 1.3148x; 1.0372x over previous
#include <cuda_runtime.h>
#include <cstdint>

// Problem constants
#define KS    5
#define NTAP  25
#define OH    508
#define OW    508
#define IH    512
#define IW    512
#define CI    3
#define BATCH 8
#define PLANE (OH * OW)              // 258064
#define WTOT  (BATCH * CI * PLANE)   // 6193536

// Band decomposition: each work item = TH full-width output rows of one batch
#define TH     2
#define NBAND  (OH / TH)             // 254
#define NWORK  (NBAND * BATCH)       // 2032
#define NTHR   256
#define NF4    (TH * (OW / 4))       // 254 float4 outputs per band
#define GRIDX  444                   // 148 SMs x 3 CTAs (persistent)

// SMEM: ring of kernel-row stages only (no tensor tile)
#define TAPB        (TH * OW * 4)         // 4064 B per tap
#define ROWB        (KS * TAPB)           // 20320 B per kernel-row stage
#define RING        3
#define MBAR_OFF    (RING * ROWB)         // 60960 (16B aligned)
#define SMEM_BYTES  (MBAR_OFF + 64)

// ---- PTX helpers ----
__device__ __forceinline__ void mbar_init(uint32_t a, uint32_t cnt) {
    asm volatile("mbarrier.init.shared.b64 [%0], %1;" :: "r"(a), "r"(cnt) : "memory");
}
__device__ __forceinline__ void mbar_expect_tx(uint32_t a, uint32_t bytes) {
    asm volatile("mbarrier.arrive.expect_tx.shared.b64 _, [%0], %1;"
                 :: "r"(a), "r"(bytes) : "memory");
}
__device__ __forceinline__ void mbar_arrive(uint32_t a) {
    asm volatile("mbarrier.arrive.shared.b64 _, [%0];" :: "r"(a) : "memory");
}
__device__ __forceinline__ void mbar_wait(uint32_t a, uint32_t parity) {
    asm volatile(
        "{\n\t.reg .pred P1;\n\t"
        "WAIT_%=:\n\t"
        "mbarrier.try_wait.parity.acquire.cta.shared::cta.b64 P1, [%0], %1, 0x989680;\n\t"
        "@P1 bra.uni DONE_%=;\n\t"
        "bra.uni WAIT_%=;\n\t"
        "DONE_%=:\n\t}"
        :: "r"(a), "r"(parity) : "memory");
}
__device__ __forceinline__ void bulk_g2s(uint32_t dst, const void* src,
                                         uint32_t bytes, uint32_t mbar) {
    asm volatile(
        "cp.async.bulk.shared::cluster.global.mbarrier::complete_tx::bytes "
        "[%0], [%1], %2, [%3];"
        :: "r"(dst), "l"(src), "r"(bytes), "r"(mbar) : "memory");
}

// stage kernel-row r (global row counter) into ring slot r%RING
__device__ __forceinline__ void stage_row(const float* __restrict__ kern,
                                          uint32_t sbase, uint32_t mb_full0,
                                          int bid, int r) {
    const int q  = r / KS;          // q-th band of this CTA
    const int di = r % KS;
    const int w  = bid + q * GRIDX; // global work id (caller guarantees < NWORK)
    const int band = w % NBAND;
    const int b    = w / NBAND;
    const float* src = kern + ((size_t)b * NTAP + di * KS) * PLANE
                            + (size_t)band * TH * OW;
    const int slot = r % RING;
    const uint32_t mb = mb_full0 + 8u * slot;
    mbar_expect_tx(mb, ROWB);
    #pragma unroll
    for (int t = 0; t < KS; ++t)
        bulk_g2s(sbase + (uint32_t)(slot * ROWB + t * TAPB),
                 src + (size_t)t * PLANE, TAPB, mb);
}

__global__ __launch_bounds__(NTHR, 3)
void apply_kernels_k(const float* __restrict__ kern,   // [8][25][508][508]
                     const float* __restrict__ tens,   // [8][3][512][512]
                     float* __restrict__ out)          // weighted ++ kernel_sum
{
    extern __shared__ char smem[];
    const uint32_t sbase = (uint32_t)__cvta_generic_to_shared(smem);

    const int bid = blockIdx.x;
    const int tid = threadIdx.x;

    const uint32_t mb_full0 = sbase + MBAR_OFF;            // full[3]
    const uint32_t mb_emp0  = sbase + MBAR_OFF + 8 * RING; // empty[3]

    if (tid == 0) {
        #pragma unroll
        for (int s = 0; s < RING; ++s) {
            mbar_init(mb_full0 + 8u * s, 1);
            mbar_init(mb_emp0  + 8u * s, NTHR);
        }
    }
    __syncthreads();

    // number of bands this CTA owns
    int nb = 0;
    for (int w = bid; w < NWORK; w += GRIDX) ++nb;
    const int rows_total = nb * KS;

    // ---- prologue: stage first RING kernel-rows ----
    if (tid == 0) {
        #pragma unroll
        for (int r = 0; r < RING; ++r) stage_row(kern, sbase, mb_full0, bid, r);
    }

    // per-thread output slot within a band (threads 254/255 duplicate 253)
    const int f  = min(tid, NF4 - 1);
    const int ro = f / (OW / 4);
    const int c4 = f % (OW / 4);
    const int j  = c4 * 4;

    int r = 0;
    for (int q = 0, w = bid; w < NWORK; ++q, w += GRIDX) {
        const int band = w % NBAND;
        const int b    = w / NBAND;
        const int i0   = band * TH;
        const int irow = i0 + ro;          // this thread's output row

        float acc[CI][4], ss[4];
        #pragma unroll
        for (int c = 0; c < CI; ++c)
            #pragma unroll
            for (int l = 0; l < 4; ++l) acc[c][l] = 0.f;
        #pragma unroll
        for (int l = 0; l < 4; ++l) ss[l] = 0.f;

        #pragma unroll
        for (int di = 0; di < KS; ++di, ++r) {
            const int slot = r % RING;
            const uint32_t par = (uint32_t)((r / RING) & 1);

            // issue tensor loads (L2-hot) BEFORE the ring wait to hide latency
            float rT[CI][8];
            #pragma unroll
            for (int c = 0; c < CI; ++c) {
                const float* tp = tens + (((size_t)b * CI + c) * IH + (irow + di)) * IW + j;
                const float4 ta = __ldg(reinterpret_cast<const float4*>(tp));
                const float4 tb = __ldg(reinterpret_cast<const float4*>(tp + 4));
                rT[c][0]=ta.x; rT[c][1]=ta.y; rT[c][2]=ta.z; rT[c][3]=ta.w;
                rT[c][4]=tb.x; rT[c][5]=tb.y; rT[c][6]=tb.z; rT[c][7]=tb.w;
            }

            mbar_wait(mb_full0 + 8u * slot, par);

            const char* rowp = smem + slot * ROWB + ro * (OW * 4) + c4 * 16;
            #pragma unroll
            for (int dj = 0; dj < KS; ++dj) {
                const float4 k4 = *reinterpret_cast<const float4*>(rowp + dj * TAPB);
                const float kv[4] = {k4.x, k4.y, k4.z, k4.w};
                #pragma unroll
                for (int l = 0; l < 4; ++l) {
                    ss[l] += kv[l];
                    #pragma unroll
                    for (int c = 0; c < CI; ++c)
                        acc[c][l] = fmaf(kv[l], rT[c][l + dj], acc[c][l]);
                }
            }

            mbar_arrive(mb_emp0 + 8u * slot);

            // refill this slot with row r+RING (continuous across bands)
            if (tid == 0 && r + RING < rows_total) {
                mbar_wait(mb_emp0 + 8u * slot, par);
                stage_row(kern, sbase, mb_full0, bid, r + RING);
            }
        }

        // ---- stores for this band ----
        const size_t pix = (size_t)irow * OW + j;
        #pragma unroll
        for (int c = 0; c < CI; ++c)
            *reinterpret_cast<float4*>(&out[((size_t)b * CI + c) * PLANE + pix]) =
                make_float4(acc[c][0], acc[c][1], acc[c][2], acc[c][3]);
        *reinterpret_cast<float4*>(&out[WTOT + (size_t)b * PLANE + pix]) =
            make_float4(ss[0], ss[1], ss[2], ss[3]);
    }
}

extern "C" void kernel_launch(void* const* d_in, const int* in_sizes, int n_in,
                              void* d_out, int out_size)
{
    const float* kern = (const float*)d_in[0];   // (8, 25, 508, 508)
    const float* tens = (const float*)d_in[1];   // (8, 3, 512, 512)
    float* out = (float*)d_out;

    cudaFuncSetAttribute(apply_kernels_k,
                         cudaFuncAttributeMaxDynamicSharedMemorySize, SMEM_BYTES);

    dim3 block(NTHR, 1, 1);        // 256 threads
    dim3 grid(GRIDX, 1, 1);        // 444 persistent CTAs (148 SMs x 3)
    apply_kernels_k<<<grid, block, SMEM_BYTES>>>(kern, tens, out);
}

// round 9
// speedup vs baseline: 1.3298x; 1.0114x over previous
#include <cuda_runtime.h>
#include <cstdint>

// Problem constants
#define KS    5
#define NTAP  25
#define OH    508
#define OW    508
#define IH    512
#define IW    512
#define CI    3
#define BATCH 8
#define PLANE (OH * OW)              // 258064
#define WTOT  (BATCH * CI * PLANE)   // 6193536

// Band decomposition: each work item = TH full-width output rows of one batch
#define TH     2
#define NBAND  (OH / TH)             // 254
#define NWORK  (NBAND * BATCH)       // 2032
#define NCOMP  256                   // compute threads
#define NTHR   288                   // + 1 producer warp
#define NF4    (TH * (OW / 4))       // 254 float4 outputs per band
#define GRIDX  444                   // 148 SMs x 3 CTAs (persistent)

// SMEM: ring of kernel-row stages
#define TAPB        (TH * OW * 4)         // 4064 B per tap
#define ROWB        (KS * TAPB)           // 20320 B per kernel-row stage
#define RING        3
#define MBAR_OFF    (RING * ROWB)         // 60960 (16B aligned)
#define SMEM_BYTES  (MBAR_OFF + 64)

// ---- PTX helpers ----
__device__ __forceinline__ void mbar_init(uint32_t a, uint32_t cnt) {
    asm volatile("mbarrier.init.shared.b64 [%0], %1;" :: "r"(a), "r"(cnt) : "memory");
}
__device__ __forceinline__ void mbar_expect_tx(uint32_t a, uint32_t bytes) {
    asm volatile("mbarrier.arrive.expect_tx.shared.b64 _, [%0], %1;"
                 :: "r"(a), "r"(bytes) : "memory");
}
__device__ __forceinline__ void mbar_arrive(uint32_t a) {
    asm volatile("mbarrier.arrive.shared.b64 _, [%0];" :: "r"(a) : "memory");
}
__device__ __forceinline__ void mbar_wait(uint32_t a, uint32_t parity) {
    asm volatile(
        "{\n\t.reg .pred P1;\n\t"
        "WAIT_%=:\n\t"
        "mbarrier.try_wait.parity.acquire.cta.shared::cta.b64 P1, [%0], %1, 0x989680;\n\t"
        "@P1 bra.uni DONE_%=;\n\t"
        "bra.uni WAIT_%=;\n\t"
        "DONE_%=:\n\t}"
        :: "r"(a), "r"(parity) : "memory");
}
__device__ __forceinline__ void bulk_g2s(uint32_t dst, const void* src,
                                         uint32_t bytes, uint32_t mbar) {
    asm volatile(
        "cp.async.bulk.shared::cluster.global.mbarrier::complete_tx::bytes "
        "[%0], [%1], %2, [%3];"
        :: "r"(dst), "l"(src), "r"(bytes), "r"(mbar) : "memory");
}

// stage kernel-row r (global row counter) into ring slot r%RING
__device__ __forceinline__ void stage_row(const float* __restrict__ kern,
                                          uint32_t sbase, uint32_t mb_full0,
                                          int bid, int r) {
    const int q  = r / KS;          // q-th band of this CTA
    const int di = r % KS;
    const int w  = bid + q * GRIDX; // global work id (< NWORK guaranteed)
    const int band = w % NBAND;
    const int b    = w / NBAND;
    const float* src = kern + ((size_t)b * NTAP + di * KS) * PLANE
                            + (size_t)band * TH * OW;
    const int slot = r % RING;
    const uint32_t mb = mb_full0 + 8u * slot;
    mbar_expect_tx(mb, ROWB);
    #pragma unroll
    for (int t = 0; t < KS; ++t)
        bulk_g2s(sbase + (uint32_t)(slot * ROWB + t * TAPB),
                 src + (size_t)t * PLANE, TAPB, mb);
}

__global__ __launch_bounds__(NTHR, 3)
void apply_kernels_k(const float* __restrict__ kern,   // [8][25][508][508]
                     const float* __restrict__ tens,   // [8][3][512][512]
                     float* __restrict__ out)          // weighted ++ kernel_sum
{
    extern __shared__ char smem[];
    const uint32_t sbase = (uint32_t)__cvta_generic_to_shared(smem);

    const int bid = blockIdx.x;
    const int tid = threadIdx.x;

    const uint32_t mb_full0 = sbase + MBAR_OFF;            // full[3]
    const uint32_t mb_emp0  = sbase + MBAR_OFF + 8 * RING; // empty[3]

    if (tid == 0) {
        #pragma unroll
        for (int s = 0; s < RING; ++s) {
            mbar_init(mb_full0 + 8u * s, 1);
            mbar_init(mb_emp0  + 8u * s, NCOMP / 32);      // per-warp arrives
        }
    }
    __syncthreads();

    // number of bands this CTA owns
    int nb = 0;
    for (int w = bid; w < NWORK; w += GRIDX) ++nb;
    const int rows_total = nb * KS;

    if (tid >= NCOMP) {
        // ================= PRODUCER WARP =================
        if ((tid & 31) == 0) {
            // prologue: fill the ring
            for (int r = 0; r < RING && r < rows_total; ++r)
                stage_row(kern, sbase, mb_full0, bid, r);
            // steady state: refill the moment a slot is freed
            for (int r = RING; r < rows_total; ++r) {
                const int slot = r % RING;
                const uint32_t par = (uint32_t)(((r - RING) / RING) & 1);
                mbar_wait(mb_emp0 + 8u * slot, par);
                stage_row(kern, sbase, mb_full0, bid, r);
            }
        }
        return;
    }

    // ================= COMPUTE THREADS =================
    const int f  = min(tid, NF4 - 1);     // threads 254/255 duplicate 253
    const int ro = f / (OW / 4);
    const int c4 = f % (OW / 4);
    const int j  = c4 * 4;
    const int lane = tid & 31;

    int r = 0;
    for (int q = 0, w = bid; w < NWORK; ++q, w += GRIDX) {
        const int band = w % NBAND;
        const int b    = w / NBAND;
        const int irow = band * TH + ro;   // this thread's output row

        float acc[CI][4], ss[4];
        #pragma unroll
        for (int c = 0; c < CI; ++c)
            #pragma unroll
            for (int l = 0; l < 4; ++l) acc[c][l] = 0.f;
        #pragma unroll
        for (int l = 0; l < 4; ++l) ss[l] = 0.f;

        #pragma unroll
        for (int di = 0; di < KS; ++di, ++r) {
            const int slot = r % RING;
            const uint32_t par = (uint32_t)((r / RING) & 1);

            // tensor loads (L2-hot) issued BEFORE the ring wait
            float rT[CI][8];
            #pragma unroll
            for (int c = 0; c < CI; ++c) {
                const float* tp = tens + (((size_t)b * CI + c) * IH + (irow + di)) * IW + j;
                const float4 ta = __ldg(reinterpret_cast<const float4*>(tp));
                const float4 tb = __ldg(reinterpret_cast<const float4*>(tp + 4));
                rT[c][0]=ta.x; rT[c][1]=ta.y; rT[c][2]=ta.z; rT[c][3]=ta.w;
                rT[c][4]=tb.x; rT[c][5]=tb.y; rT[c][6]=tb.z; rT[c][7]=tb.w;
            }

            mbar_wait(mb_full0 + 8u * slot, par);

            const char* rowp = smem + slot * ROWB + ro * (OW * 4) + c4 * 16;
            #pragma unroll
            for (int dj = 0; dj < KS; ++dj) {
                const float4 k4 = *reinterpret_cast<const float4*>(rowp + dj * TAPB);
                const float kv[4] = {k4.x, k4.y, k4.z, k4.w};
                #pragma unroll
                for (int l = 0; l < 4; ++l) {
                    ss[l] += kv[l];
                    #pragma unroll
                    for (int c = 0; c < CI; ++c)
                        acc[c][l] = fmaf(kv[l], rT[c][l + dj], acc[c][l]);
                }
            }

            // whole-warp consumption ack: one arrive per warp
            __syncwarp();
            if (lane == 0) mbar_arrive(mb_emp0 + 8u * slot);
        }

        // ---- stores for this band ----
        const size_t pix = (size_t)irow * OW + j;
        #pragma unroll
        for (int c = 0; c < CI; ++c)
            *reinterpret_cast<float4*>(&out[((size_t)b * CI + c) * PLANE + pix]) =
                make_float4(acc[c][0], acc[c][1], acc[c][2], acc[c][3]);
        *reinterpret_cast<float4*>(&out[WTOT + (size_t)b * PLANE + pix]) =
            make_float4(ss[0], ss[1], ss[2], ss[3]);
    }
}

extern "C" void kernel_launch(void* const* d_in, const int* in_sizes, int n_in,
                              void* d_out, int out_size)
{
    const float* kern = (const float*)d_in[0];   // (8, 25, 508, 508)
    const float* tens = (const float*)d_in[1];   // (8, 3, 512, 512)
    float* out = (float*)d_out;

    cudaFuncSetAttribute(apply_kernels_k,
                         cudaFuncAttributeMaxDynamicSharedMemorySize, SMEM_BYTES);

    dim3 block(NTHR, 1, 1);        // 288 threads: 8 compute warps + 1 producer
    dim3 grid(GRIDX, 1, 1);        // 444 persistent CTAs
    apply_kernels_k<<<grid, block, SMEM_BYTES>>>(kern, tens, out);
}

// round 10
// speedup vs baseline: 1.5450x; 1.1618x over previous
#include <cuda_runtime.h>
#include <cstdint>

// Problem constants
#define KS    5
#define NTAP  25
#define OH    508
#define OW    508
#define IH    512
#define IW    512
#define CI    3
#define BATCH 8
#define PLANE (OH * OW)              // 258064
#define WTOT  (BATCH * CI * PLANE)   // 6193536

// Band decomposition: each work item = TH full-width output rows of one batch
#define TH     2
#define NBAND  (OH / TH)             // 254
#define NWORK  (NBAND * BATCH)       // 2032 = 406*5 + 2
#define NCOMP  256                   // compute threads
#define NTHR   288                   // + 1 producer warp
#define NF4    (TH * (OW / 4))       // 254 float4 outputs per band
#define GRIDX  406                   // balanced: every CTA ~5 bands

// SMEM: ring of kernel-row stages
#define TAPB        (TH * OW * 4)         // 4064 B per tap
#define ROWB        (KS * TAPB)           // 20320 B per kernel-row stage
#define RING        3
#define MBAR_OFF    (RING * ROWB)         // 60960 (16B aligned)
#define SMEM_BYTES  (MBAR_OFF + 64)

// ---- PTX helpers ----
__device__ __forceinline__ void mbar_init(uint32_t a, uint32_t cnt) {
    asm volatile("mbarrier.init.shared.b64 [%0], %1;" :: "r"(a), "r"(cnt) : "memory");
}
__device__ __forceinline__ void mbar_expect_tx(uint32_t a, uint32_t bytes) {
    asm volatile("mbarrier.arrive.expect_tx.shared.b64 _, [%0], %1;"
                 :: "r"(a), "r"(bytes) : "memory");
}
__device__ __forceinline__ void mbar_arrive(uint32_t a) {
    asm volatile("mbarrier.arrive.shared.b64 _, [%0];" :: "r"(a) : "memory");
}
__device__ __forceinline__ void mbar_wait(uint32_t a, uint32_t parity) {
    asm volatile(
        "{\n\t.reg .pred P1;\n\t"
        "WAIT_%=:\n\t"
        "mbarrier.try_wait.parity.acquire.cta.shared::cta.b64 P1, [%0], %1, 0x989680;\n\t"
        "@P1 bra.uni DONE_%=;\n\t"
        "bra.uni WAIT_%=;\n\t"
        "DONE_%=:\n\t}"
        :: "r"(a), "r"(parity) : "memory");
}
__device__ __forceinline__ uint64_t policy_evict_first() {
    uint64_t p;
    asm volatile("createpolicy.fractional.L2::evict_first.b64 %0, 1.0;" : "=l"(p));
    return p;
}
__device__ __forceinline__ void bulk_g2s_ef(uint32_t dst, const void* src,
                                            uint32_t bytes, uint32_t mbar,
                                            uint64_t pol) {
    asm volatile(
        "cp.async.bulk.shared::cluster.global.mbarrier::complete_tx::bytes"
        ".L2::cache_hint [%0], [%1], %2, [%3], %4;"
        :: "r"(dst), "l"(src), "r"(bytes), "r"(mbar), "l"(pol) : "memory");
}
__device__ __forceinline__ void stcs4(float* p, float4 v) {
    asm volatile("st.global.cs.v4.f32 [%0], {%1,%2,%3,%4};"
                 :: "l"(p), "f"(v.x), "f"(v.y), "f"(v.z), "f"(v.w));
}

// stage kernel-row r (global row counter) into ring slot r%RING
__device__ __forceinline__ void stage_row(const float* __restrict__ kern,
                                          uint32_t sbase, uint32_t mb_full0,
                                          int bid, int r, uint64_t pol) {
    const int q  = r / KS;          // q-th band of this CTA
    const int di = r % KS;
    const int w  = bid + q * GRIDX; // global work id (< NWORK guaranteed)
    const int band = w % NBAND;
    const int b    = w / NBAND;
    const float* src = kern + ((size_t)b * NTAP + di * KS) * PLANE
                            + (size_t)band * TH * OW;
    const int slot = r % RING;
    const uint32_t mb = mb_full0 + 8u * slot;
    mbar_expect_tx(mb, ROWB);
    #pragma unroll
    for (int t = 0; t < KS; ++t)
        bulk_g2s_ef(sbase + (uint32_t)(slot * ROWB + t * TAPB),
                    src + (size_t)t * PLANE, TAPB, mb, pol);
}

__global__ __launch_bounds__(NTHR, 3)
void apply_kernels_k(const float* __restrict__ kern,   // [8][25][508][508]
                     const float* __restrict__ tens,   // [8][3][512][512]
                     float* __restrict__ out)          // weighted ++ kernel_sum
{
    extern __shared__ char smem[];
    const uint32_t sbase = (uint32_t)__cvta_generic_to_shared(smem);

    const int bid = blockIdx.x;
    const int tid = threadIdx.x;

    const uint32_t mb_full0 = sbase + MBAR_OFF;            // full[3]
    const uint32_t mb_emp0  = sbase + MBAR_OFF + 8 * RING; // empty[3]

    if (tid == 0) {
        #pragma unroll
        for (int s = 0; s < RING; ++s) {
            mbar_init(mb_full0 + 8u * s, 1);
            mbar_init(mb_emp0  + 8u * s, NCOMP / 32);      // per-warp arrives
        }
    }
    __syncthreads();

    // number of bands this CTA owns
    int nb = 0;
    for (int w = bid; w < NWORK; w += GRIDX) ++nb;
    const int rows_total = nb * KS;

    if (tid >= NCOMP) {
        // ================= PRODUCER WARP =================
        if ((tid & 31) == 0) {
            const uint64_t pol = policy_evict_first();
            for (int r = 0; r < RING && r < rows_total; ++r)
                stage_row(kern, sbase, mb_full0, bid, r, pol);
            for (int r = RING; r < rows_total; ++r) {
                const int slot = r % RING;
                const uint32_t par = (uint32_t)(((r - RING) / RING) & 1);
                mbar_wait(mb_emp0 + 8u * slot, par);
                stage_row(kern, sbase, mb_full0, bid, r, pol);
            }
        }
        return;
    }

    // ================= COMPUTE THREADS =================
    const int f  = min(tid, NF4 - 1);     // threads 254/255 duplicate 253
    const int ro = f / (OW / 4);
    const int c4 = f % (OW / 4);
    const int j  = c4 * 4;
    const int lane = tid & 31;

    int r = 0;
    for (int q = 0, w = bid; w < NWORK; ++q, w += GRIDX) {
        const int band = w % NBAND;
        const int b    = w / NBAND;
        const int irow = band * TH + ro;   // this thread's output row

        float acc[CI][4], ss[4];
        #pragma unroll
        for (int c = 0; c < CI; ++c)
            #pragma unroll
            for (int l = 0; l < 4; ++l) acc[c][l] = 0.f;
        #pragma unroll
        for (int l = 0; l < 4; ++l) ss[l] = 0.f;

        #pragma unroll
        for (int di = 0; di < KS; ++di, ++r) {
            const int slot = r % RING;
            const uint32_t par = (uint32_t)((r / RING) & 1);

            // tensor loads (L2-resident) issued BEFORE the ring wait
            float rT[CI][8];
            #pragma unroll
            for (int c = 0; c < CI; ++c) {
                const float* tp = tens + (((size_t)b * CI + c) * IH + (irow + di)) * IW + j;
                const float4 ta = __ldg(reinterpret_cast<const float4*>(tp));
                const float4 tb = __ldg(reinterpret_cast<const float4*>(tp + 4));
                rT[c][0]=ta.x; rT[c][1]=ta.y; rT[c][2]=ta.z; rT[c][3]=ta.w;
                rT[c][4]=tb.x; rT[c][5]=tb.y; rT[c][6]=tb.z; rT[c][7]=tb.w;
            }

            mbar_wait(mb_full0 + 8u * slot, par);

            const char* rowp = smem + slot * ROWB + ro * (OW * 4) + c4 * 16;
            #pragma unroll
            for (int dj = 0; dj < KS; ++dj) {
                const float4 k4 = *reinterpret_cast<const float4*>(rowp + dj * TAPB);
                const float kv[4] = {k4.x, k4.y, k4.z, k4.w};
                #pragma unroll
                for (int l = 0; l < 4; ++l) {
                    ss[l] += kv[l];
                    #pragma unroll
                    for (int c = 0; c < CI; ++c)
                        acc[c][l] = fmaf(kv[l], rT[c][l + dj], acc[c][l]);
                }
            }

            // whole-warp consumption ack: one arrive per warp
            __syncwarp();
            if (lane == 0) mbar_arrive(mb_emp0 + 8u * slot);
        }

        // ---- stores for this band (streaming: never re-read) ----
        const size_t pix = (size_t)irow * OW + j;
        #pragma unroll
        for (int c = 0; c < CI; ++c)
            stcs4(&out[((size_t)b * CI + c) * PLANE + pix],
                  make_float4(acc[c][0], acc[c][1], acc[c][2], acc[c][3]));
        stcs4(&out[WTOT + (size_t)b * PLANE + pix],
              make_float4(ss[0], ss[1], ss[2], ss[3]));
    }
}

extern "C" void kernel_launch(void* const* d_in, const int* in_sizes, int n_in,
                              void* d_out, int out_size)
{
    const float* kern = (const float*)d_in[0];   // (8, 25, 508, 508)
    const float* tens = (const float*)d_in[1];   // (8, 3, 512, 512)
    float* out = (float*)d_out;

    cudaFuncSetAttribute(apply_kernels_k,
                         cudaFuncAttributeMaxDynamicSharedMemorySize, SMEM_BYTES);

    dim3 block(NTHR, 1, 1);        // 288 threads: 8 compute warps + 1 producer
    dim3 grid(GRIDX, 1, 1);        // 406 persistent CTAs, 5 bands each
    apply_kernels_k<<<grid, block, SMEM_BYTES>>>(kern, tens, out);
}

// round 13
// speedup vs baseline: 1.5910x; 1.0298x over previous
#include <cuda_runtime.h>
#include <cstdint>

// Problem constants
#define KS    5
#define NTAP  25
#define OH    508
#define OW    508
#define IH    512
#define IW    512
#define CI    3
#define BATCH 8
#define PLANE (OH * OW)              // 258064
#define WTOT  (BATCH * CI * PLANE)   // 6193536

// Band decomposition: each work item = TH full-width output rows of one batch
#define TH     2
#define NBAND  (OH / TH)             // 254
#define NWORK  (NBAND * BATCH)       // 2032
#define NCOMP  256                   // compute threads
#define NTHR   288                   // + 1 producer warp
#define NF4    (TH * (OW / 4))       // 254 float4 outputs per band
#define GRIDX  444                   // 148 SMs x 3 CTAs, uniform occupancy

// SMEM: ring of kernel-row stages
#define TAPB        (TH * OW * 4)         // 4064 B per tap
#define ROWB        (KS * TAPB)           // 20320 B per kernel-row stage
#define RING        3
#define MBAR_OFF    (RING * ROWB)         // 60960 (16B aligned)
#define SMEM_BYTES  (MBAR_OFF + 64)

// ---- PTX helpers ----
__device__ __forceinline__ void mbar_init(uint32_t a, uint32_t cnt) {
    asm volatile("mbarrier.init.shared.b64 [%0], %1;" :: "r"(a), "r"(cnt) : "memory");
}
__device__ __forceinline__ void mbar_expect_tx(uint32_t a, uint32_t bytes) {
    asm volatile("mbarrier.arrive.expect_tx.shared.b64 _, [%0], %1;"
                 :: "r"(a), "r"(bytes) : "memory");
}
__device__ __forceinline__ void mbar_arrive(uint32_t a) {
    asm volatile("mbarrier.arrive.shared.b64 _, [%0];" :: "r"(a) : "memory");
}
__device__ __forceinline__ void mbar_wait(uint32_t a, uint32_t parity) {
    asm volatile(
        "{\n\t.reg .pred P1;\n\t"
        "WAIT_%=:\n\t"
        "mbarrier.try_wait.parity.acquire.cta.shared::cta.b64 P1, [%0], %1, 0x989680;\n\t"
        "@P1 bra.uni DONE_%=;\n\t"
        "bra.uni WAIT_%=;\n\t"
        "DONE_%=:\n\t}"
        :: "r"(a), "r"(parity) : "memory");
}
__device__ __forceinline__ uint64_t policy_evict_first() {
    uint64_t p;
    asm volatile("createpolicy.fractional.L2::evict_first.b64 %0, 1.0;" : "=l"(p));
    return p;
}
__device__ __forceinline__ void bulk_g2s_ef(uint32_t dst, const void* src,
                                            uint32_t bytes, uint32_t mbar,
                                            uint64_t pol) {
    asm volatile(
        "cp.async.bulk.shared::cluster.global.mbarrier::complete_tx::bytes"
        ".L2::cache_hint [%0], [%1], %2, [%3], %4;"
        :: "r"(dst), "l"(src), "r"(bytes), "r"(mbar), "l"(pol) : "memory");
}
__device__ __forceinline__ void stcs4(float* p, float4 v) {
    asm volatile("st.global.cs.v4.f32 [%0], {%1,%2,%3,%4};"
                 :: "l"(p), "f"(v.x), "f"(v.y), "f"(v.z), "f"(v.w));
}

// stage kernel-row r (global row counter) into ring slot r%RING
__device__ __forceinline__ void stage_row(const float* __restrict__ kern,
                                          uint32_t sbase, uint32_t mb_full0,
                                          int bid, int r, uint64_t pol) {
    const int q  = r / KS;          // q-th band of this CTA
    const int di = r % KS;
    const int w  = bid + q * GRIDX; // global work id (< NWORK guaranteed)
    const int band = w % NBAND;
    const int b    = w / NBAND;
    const float* src = kern + ((size_t)b * NTAP + di * KS) * PLANE
                            + (size_t)band * TH * OW;
    const int slot = r % RING;
    const uint32_t mb = mb_full0 + 8u * slot;
    mbar_expect_tx(mb, ROWB);
    #pragma unroll
    for (int t = 0; t < KS; ++t)
        bulk_g2s_ef(sbase + (uint32_t)(slot * ROWB + t * TAPB),
                    src + (size_t)t * PLANE, TAPB, mb, pol);
}

__global__ __launch_bounds__(NTHR, 3)
void apply_kernels_k(const float* __restrict__ kern,   // [8][25][508][508]
                     const float* __restrict__ tens,   // [8][3][512][512]
                     float* __restrict__ out)          // weighted ++ kernel_sum
{
    extern __shared__ char smem[];
    const uint32_t sbase = (uint32_t)__cvta_generic_to_shared(smem);

    const int bid = blockIdx.x;
    const int tid = threadIdx.x;

    const uint32_t mb_full0 = sbase + MBAR_OFF;            // full[3]
    const uint32_t mb_emp0  = sbase + MBAR_OFF + 8 * RING; // empty[3]

    if (tid == 0) {
        #pragma unroll
        for (int s = 0; s < RING; ++s) {
            mbar_init(mb_full0 + 8u * s, 1);
            mbar_init(mb_emp0  + 8u * s, NCOMP / 32);      // per-warp arrives
        }
    }
    __syncthreads();

    // number of bands this CTA owns
    int nb = 0;
    for (int w = bid; w < NWORK; w += GRIDX) ++nb;
    const int rows_total = nb * KS;

    if (tid >= NCOMP) {
        // ================= PRODUCER WARP =================
        if ((tid & 31) == 0) {
            const uint64_t pol = policy_evict_first();
            for (int r = 0; r < RING && r < rows_total; ++r)
                stage_row(kern, sbase, mb_full0, bid, r, pol);
            for (int r = RING; r < rows_total; ++r) {
                const int slot = r % RING;
                const uint32_t par = (uint32_t)(((r - RING) / RING) & 1);
                mbar_wait(mb_emp0 + 8u * slot, par);
                stage_row(kern, sbase, mb_full0, bid, r, pol);
            }
        }
        return;
    }

    // ================= COMPUTE THREADS =================
    const int f  = min(tid, NF4 - 1);     // threads 254/255 duplicate 253
    const int ro = f / (OW / 4);
    const int c4 = f % (OW / 4);
    const int j  = c4 * 4;
    const int lane = tid & 31;

    int r = 0;
    for (int q = 0, w = bid; w < NWORK; ++q, w += GRIDX) {
        const int band = w % NBAND;
        const int b    = w / NBAND;
        const int irow = band * TH + ro;   // this thread's output row

        float acc[CI][4], ss[4];
        #pragma unroll
        for (int c = 0; c < CI; ++c)
            #pragma unroll
            for (int l = 0; l < 4; ++l) acc[c][l] = 0.f;
        #pragma unroll
        for (int l = 0; l < 4; ++l) ss[l] = 0.f;

        #pragma unroll
        for (int di = 0; di < KS; ++di, ++r) {
            const int slot = r % RING;
            const uint32_t par = (uint32_t)((r / RING) & 1);

            // tensor loads (L2-resident) issued BEFORE the ring wait
            float rT[CI][8];
            #pragma unroll
            for (int c = 0; c < CI; ++c) {
                const float* tp = tens + (((size_t)b * CI + c) * IH + (irow + di)) * IW + j;
                const float4 ta = __ldg(reinterpret_cast<const float4*>(tp));
                const float4 tb = __ldg(reinterpret_cast<const float4*>(tp + 4));
                rT[c][0]=ta.x; rT[c][1]=ta.y; rT[c][2]=ta.z; rT[c][3]=ta.w;
                rT[c][4]=tb.x; rT[c][5]=tb.y; rT[c][6]=tb.z; rT[c][7]=tb.w;
            }

            mbar_wait(mb_full0 + 8u * slot, par);

            const char* rowp = smem + slot * ROWB + ro * (OW * 4) + c4 * 16;
            #pragma unroll
            for (int dj = 0; dj < KS; ++dj) {
                const float4 k4 = *reinterpret_cast<const float4*>(rowp + dj * TAPB);
                const float kv[4] = {k4.x, k4.y, k4.z, k4.w};
                #pragma unroll
                for (int l = 0; l < 4; ++l) {
                    ss[l] += kv[l];
                    #pragma unroll
                    for (int c = 0; c < CI; ++c)
                        acc[c][l] = fmaf(kv[l], rT[c][l + dj], acc[c][l]);
                }
            }

            // whole-warp consumption ack: one arrive per warp
            __syncwarp();
            if (lane == 0) mbar_arrive(mb_emp0 + 8u * slot);
        }

        // ---- stores for this band (streaming: never re-read) ----
        const size_t pix = (size_t)irow * OW + j;
        #pragma unroll
        for (int c = 0; c < CI; ++c)
            stcs4(&out[((size_t)b * CI + c) * PLANE + pix],
                  make_float4(acc[c][0], acc[c][1], acc[c][2], acc[c][3]));
        stcs4(&out[WTOT + (size_t)b * PLANE + pix],
              make_float4(ss[0], ss[1], ss[2], ss[3]));
    }
}

extern "C" void kernel_launch(void* const* d_in, const int* in_sizes, int n_in,
                              void* d_out, int out_size)
{
    const float* kern = (const float*)d_in[0];   // (8, 25, 508, 508)
    const float* tens = (const float*)d_in[1];   // (8, 3, 512, 512)
    float* out = (float*)d_out;

    cudaFuncSetAttribute(apply_kernels_k,
                         cudaFuncAttributeMaxDynamicSharedMemorySize, SMEM_BYTES);

    dim3 block(NTHR, 1, 1);        // 288 threads: 8 compute warps + 1 producer
    dim3 grid(GRIDX, 1, 1);        // 444 persistent CTAs, uniform 3/SM
    apply_kernels_k<<<grid, block, SMEM_BYTES>>>(kern, tens, out);
}

// round 16
// speedup vs baseline: 1.6019x; 1.0068x over previous
#include <cuda_runtime.h>
#include <cstdint>

// Problem constants
#define KS    5
#define NTAP  25
#define OH    508
#define OW    508
#define IH    512
#define IW    512
#define CI    3
#define BATCH 8
#define PLANE (OH * OW)              // 258064
#define WTOT  (BATCH * CI * PLANE)   // 6193536

// Band decomposition: each work item = TH full-width output rows of one batch
#define TH     2
#define NBAND  (OH / TH)             // 254
#define NWORK  (NBAND * BATCH)       // 2032
#define NCOMP  256                   // compute threads
#define NTHR   288                   // + 1 producer warp
#define NF4    (TH * (OW / 4))       // 254 float4 outputs per band
#define GRIDX  296                   // 148 SMs x 2 CTAs, uniform occupancy

// SMEM: ring of kernel-row stages
#define TAPB        (TH * OW * 4)         // 4064 B per tap
#define ROWB        (KS * TAPB)           // 20320 B per kernel-row stage
#define RING        4
#define MBAR_OFF    (RING * ROWB)         // 81280 (16B aligned)
#define SMEM_BYTES  (MBAR_OFF + 64)       // 81344

// ---- PTX helpers ----
__device__ __forceinline__ void mbar_init(uint32_t a, uint32_t cnt) {
    asm volatile("mbarrier.init.shared.b64 [%0], %1;" :: "r"(a), "r"(cnt) : "memory");
}
__device__ __forceinline__ void mbar_expect_tx(uint32_t a, uint32_t bytes) {
    asm volatile("mbarrier.arrive.expect_tx.shared.b64 _, [%0], %1;"
                 :: "r"(a), "r"(bytes) : "memory");
}
__device__ __forceinline__ void mbar_arrive(uint32_t a) {
    asm volatile("mbarrier.arrive.shared.b64 _, [%0];" :: "r"(a) : "memory");
}
__device__ __forceinline__ void mbar_wait(uint32_t a, uint32_t parity) {
    asm volatile(
        "{\n\t.reg .pred P1;\n\t"
        "WAIT_%=:\n\t"
        "mbarrier.try_wait.parity.acquire.cta.shared::cta.b64 P1, [%0], %1, 0x989680;\n\t"
        "@P1 bra.uni DONE_%=;\n\t"
        "bra.uni WAIT_%=;\n\t"
        "DONE_%=:\n\t}"
        :: "r"(a), "r"(parity) : "memory");
}
__device__ __forceinline__ uint64_t policy_evict_first() {
    uint64_t p;
    asm volatile("createpolicy.fractional.L2::evict_first.b64 %0, 1.0;" : "=l"(p));
    return p;
}
__device__ __forceinline__ void bulk_g2s_ef(uint32_t dst, const void* src,
                                            uint32_t bytes, uint32_t mbar,
                                            uint64_t pol) {
    asm volatile(
        "cp.async.bulk.shared::cluster.global.mbarrier::complete_tx::bytes"
        ".L2::cache_hint [%0], [%1], %2, [%3], %4;"
        :: "r"(dst), "l"(src), "r"(bytes), "r"(mbar), "l"(pol) : "memory");
}
__device__ __forceinline__ void stcs4(float* p, float4 v) {
    asm volatile("st.global.cs.v4.f32 [%0], {%1,%2,%3,%4};"
                 :: "l"(p), "f"(v.x), "f"(v.y), "f"(v.z), "f"(v.w));
}

// stage kernel-row r (global row counter) into ring slot r%RING
__device__ __forceinline__ void stage_row(const float* __restrict__ kern,
                                          uint32_t sbase, uint32_t mb_full0,
                                          int bid, int r, uint64_t pol) {
    const int q  = r / KS;          // q-th band of this CTA
    const int di = r % KS;
    const int w  = bid + q * GRIDX; // global work id (< NWORK guaranteed)
    const int band = w % NBAND;
    const int b    = w / NBAND;
    const float* src = kern + ((size_t)b * NTAP + di * KS) * PLANE
                            + (size_t)band * TH * OW;
    const int slot = r % RING;
    const uint32_t mb = mb_full0 + 8u * slot;
    mbar_expect_tx(mb, ROWB);
    #pragma unroll
    for (int t = 0; t < KS; ++t)
        bulk_g2s_ef(sbase + (uint32_t)(slot * ROWB + t * TAPB),
                    src + (size_t)t * PLANE, TAPB, mb, pol);
}

// load 8 tensor floats per channel for (batch b, tensor row trow, col j)
__device__ __forceinline__ void loadT(float (&rT)[CI][8],
                                      const float* __restrict__ tens,
                                      int b, int trow, int j) {
    #pragma unroll
    for (int c = 0; c < CI; ++c) {
        const float* tp = tens + (((size_t)b * CI + c) * IH + trow) * IW + j;
        const float4 ta = __ldg(reinterpret_cast<const float4*>(tp));
        const float4 tb = __ldg(reinterpret_cast<const float4*>(tp + 4));
        rT[c][0]=ta.x; rT[c][1]=ta.y; rT[c][2]=ta.z; rT[c][3]=ta.w;
        rT[c][4]=tb.x; rT[c][5]=tb.y; rT[c][6]=tb.z; rT[c][7]=tb.w;
    }
}

__global__ __launch_bounds__(NTHR, 2)
void apply_kernels_k(const float* __restrict__ kern,   // [8][25][508][508]
                     const float* __restrict__ tens,   // [8][3][512][512]
                     float* __restrict__ out)          // weighted ++ kernel_sum
{
    extern __shared__ char smem[];
    const uint32_t sbase = (uint32_t)__cvta_generic_to_shared(smem);

    const int bid = blockIdx.x;
    const int tid = threadIdx.x;

    const uint32_t mb_full0 = sbase + MBAR_OFF;            // full[RING]
    const uint32_t mb_emp0  = sbase + MBAR_OFF + 8 * RING; // empty[RING]

    if (tid == 0) {
        #pragma unroll
        for (int s = 0; s < RING; ++s) {
            mbar_init(mb_full0 + 8u * s, 1);
            mbar_init(mb_emp0  + 8u * s, NCOMP / 32);      // per-warp arrives
        }
    }
    __syncthreads();

    // number of bands this CTA owns
    int nb = 0;
    for (int w = bid; w < NWORK; w += GRIDX) ++nb;
    const int rows_total = nb * KS;

    if (tid >= NCOMP) {
        // ================= PRODUCER WARP =================
        if ((tid & 31) == 0) {
            const uint64_t pol = policy_evict_first();
            const int pre = (RING < rows_total) ? RING : rows_total;
            for (int r = 0; r < pre; ++r)
                stage_row(kern, sbase, mb_full0, bid, r, pol);
            for (int r = RING; r < rows_total; ++r) {
                const int slot = r % RING;
                const uint32_t par = (uint32_t)(((r - RING) / RING) & 1);
                mbar_wait(mb_emp0 + 8u * slot, par);
                stage_row(kern, sbase, mb_full0, bid, r, pol);
            }
        }
        return;
    }

    // ================= COMPUTE THREADS =================
    const int f  = min(tid, NF4 - 1);     // threads 254/255 duplicate 253
    const int ro = f / (OW / 4);
    const int c4 = f % (OW / 4);
    const int j  = c4 * 4;
    const int lane = tid & 31;

    // band-walk state
    int di = 0;
    int w  = bid;
    int b    = w / NBAND;
    int irow = (w % NBAND) * TH + ro;

    float acc[CI][4], ss[4];
    #pragma unroll
    for (int c = 0; c < CI; ++c)
        #pragma unroll
        for (int l = 0; l < 4; ++l) acc[c][l] = 0.f;
    #pragma unroll
    for (int l = 0; l < 4; ++l) ss[l] = 0.f;

    // double-buffered tensor registers; prologue: row 0
    float rT0[CI][8], rT1[CI][8];
    loadT(rT0, tens, b, irow, j);

    // one pipeline step: consume row r from rTc, prefetch row r+1 into rTn
    auto step = [&](int r, float (&rTc)[CI][8], float (&rTn)[CI][8], bool has_next) {
        const int slot = r % RING;
        const uint32_t par = (uint32_t)((r / RING) & 1);
        mbar_wait(mb_full0 + 8u * slot, par);

        // issue NEXT row's tensor loads now — full row of time to land
        if (has_next) {
            int di1 = di + 1, w1 = w, b1 = b, irow1 = irow;
            if (di1 == KS) {
                di1 = 0; w1 = w + GRIDX;
                b1 = w1 / NBAND; irow1 = (w1 % NBAND) * TH + ro;
            }
            loadT(rTn, tens, b1, irow1 + di1, j);
        }

        const char* rowp = smem + slot * ROWB + ro * (OW * 4) + c4 * 16;
        #pragma unroll
        for (int dj = 0; dj < KS; ++dj) {
            const float4 k4 = *reinterpret_cast<const float4*>(rowp + dj * TAPB);
            const float kv[4] = {k4.x, k4.y, k4.z, k4.w};
            #pragma unroll
            for (int l = 0; l < 4; ++l) {
                ss[l] += kv[l];
                #pragma unroll
                for (int c = 0; c < CI; ++c)
                    acc[c][l] = fmaf(kv[l], rTc[c][l + dj], acc[c][l]);
            }
        }

        __syncwarp();
        if (lane == 0) mbar_arrive(mb_emp0 + 8u * slot);

        if (++di == KS) {
            // ---- band complete: store (streaming) and reset ----
            const size_t pix = (size_t)irow * OW + j;
            #pragma unroll
            for (int c = 0; c < CI; ++c)
                stcs4(&out[((size_t)b * CI + c) * PLANE + pix],
                      make_float4(acc[c][0], acc[c][1], acc[c][2], acc[c][3]));
            stcs4(&out[WTOT + (size_t)b * PLANE + pix],
                  make_float4(ss[0], ss[1], ss[2], ss[3]));

            di = 0; w += GRIDX;
            if (w < NWORK) { b = w / NBAND; irow = (w % NBAND) * TH + ro; }
            #pragma unroll
            for (int c = 0; c < CI; ++c)
                #pragma unroll
                for (int l = 0; l < 4; ++l) acc[c][l] = 0.f;
            #pragma unroll
            for (int l = 0; l < 4; ++l) ss[l] = 0.f;
        }
    };

    // statically alternate buffers so rT stays in registers
    int r = 0;
    for (; r + 1 < rows_total; r += 2) {
        step(r,     rT0, rT1, true);
        step(r + 1, rT1, rT0, r + 2 < rows_total);
    }
    if (r < rows_total)
        step(r, rT0, rT1, false);
}

extern "C" void kernel_launch(void* const* d_in, const int* in_sizes, int n_in,
                              void* d_out, int out_size)
{
    const float* kern = (const float*)d_in[0];   // (8, 25, 508, 508)
    const float* tens = (const float*)d_in[1];   // (8, 3, 512, 512)
    float* out = (float*)d_out;

    cudaFuncSetAttribute(apply_kernels_k,
                         cudaFuncAttributeMaxDynamicSharedMemorySize, SMEM_BYTES);

    dim3 block(NTHR, 1, 1);        // 288 threads: 8 compute warps + 1 producer
    dim3 grid(GRIDX, 1, 1);        // 296 persistent CTAs, uniform 2/SM
    apply_kernels_k<<<grid, block, SMEM_BYTES>>>(kern, tens, out);
}